// round 15
// baseline (speedup 1.0000x reference)
#include <cuda_runtime.h>
#include <cuda_fp16.h>
#include <math.h>
#include <stdint.h>

#define B_  8
#define L_  4096
#define D_  512
#define M_TOTAL (B_ * L_)
#define NTILES (M_TOTAL / 128)
#define WSCALE 256.0f
#define INV_WSCALE 0.00390625f
#define BAND_TAU 1e-3f

// mega-kernel block layout (512 threads each)
#define NB_BAND 64
#define NB_REC  64
#define NB_SCAN B_
#define POOL_PER_B 256          // small-segment blocks per batch (16 warps each)
#define TAIL_PER_B 4            // tail blocks per batch (4 chunks each)
#define NB_POOL (B_ * (POOL_PER_B + TAIL_PER_B))
#define MEGA_BLOCKS (NB_BAND + NB_REC + NB_SCAN + NB_POOL)

// ------------------------------------------------------------------
// device scratch
// ------------------------------------------------------------------
__device__ __half g_w1h[D_ * D_];                  // fp16(W1*256)^T [n][k]
__device__ float g_part[4][M_TOTAL];               // per-n-tile partial logits
__device__ unsigned char g_hard[M_TOTAL];          // hard boundary bits
__device__ int g_band[M_TOTAL];                    // rows needing exact recompute
__device__ int g_count;                            // band count
__device__ int g_band_done;                        // band arrival counter
__device__ int g_rec_done;                         // recompute arrival counter
__device__ int g_scan_done[B_];                    // per-batch scan flags
__device__ int g_tail_tick[B_];                    // tail completion tickets
__device__ int g_seg_start[B_ * L_];
__device__ int g_seg_cnt[B_ * L_];
__device__ int g_nb[B_];
__device__ float g_tailpart[B_][16][D_];

// ------------------------------------------------------------------
// PTX helpers (sm_80-level, safe for compute_103 non-a)
// ------------------------------------------------------------------
#define CP_ASYNC16(dst, src) \
    asm volatile("cp.async.cg.shared.global [%0], [%1], 16;" :: "r"(dst), "l"(src))
#define CP_COMMIT() asm volatile("cp.async.commit_group;")
#define CP_WAIT(n)  asm volatile("cp.async.wait_group %0;" :: "n"(n))

__device__ __forceinline__ uint32_t smem_u32(const void* p) {
    uint32_t a;
    asm("{ .reg .u64 t; cvta.to.shared.u64 t, %1; cvt.u32.u64 %0, t; }" : "=r"(a) : "l"(p));
    return a;
}
__device__ __forceinline__ void ldsm4(uint32_t* r, uint32_t a) {
    asm volatile("ldmatrix.sync.aligned.m8n8.x4.shared.b16 {%0,%1,%2,%3}, [%4];"
                 : "=r"(r[0]), "=r"(r[1]), "=r"(r[2]), "=r"(r[3]) : "r"(a));
}
__device__ __forceinline__ void mma_f16(float* c, const uint32_t* a, const uint32_t* b) {
    asm volatile(
        "mma.sync.aligned.m16n8k16.row.col.f32.f16.f16.f32 "
        "{%0,%1,%2,%3}, {%4,%5,%6,%7}, {%8,%9}, {%0,%1,%2,%3};"
        : "+f"(c[0]), "+f"(c[1]), "+f"(c[2]), "+f"(c[3])
        : "r"(a[0]), "r"(a[1]), "r"(a[2]), "r"(a[3]), "r"(b[0]), "r"(b[1]));
}
__device__ __forceinline__ void spin_until(int* flag, int target) {
    while (atomicAdd(flag, 0) < target) { __nanosleep(64); }
}

// ------------------------------------------------------------------
// Kernel B: W1 -> transposed fp16 (x256); reset all counters/flags
// ------------------------------------------------------------------
__global__ __launch_bounds__(512)
void w1half_kernel(const float* __restrict__ W1) {
    if (blockIdx.x == 0) {
        if (threadIdx.x == 0) { g_count = 0; g_band_done = 0; g_rec_done = 0; }
        if (threadIdx.x < B_) { g_tail_tick[threadIdx.x] = 0; g_scan_done[threadIdx.x] = 0; }
    }
    int k = blockIdx.x;
    int n = threadIdx.x;
    g_w1h[n * D_ + k] = __float2half_rn(W1[k * D_ + n] * WSCALE);
}

// ------------------------------------------------------------------
// Kernel C: mma.sync fp16 GEMM (R9/R12 anchor — unchanged)
// ------------------------------------------------------------------
#define ROWB 80
#define SPLIT_TILE (128 * ROWB)              // 10240
#define OFF_B16 (2 * SPLIT_TILE)             // 20480
#define STAGE_ROWB 144
#define STAGE_TILE (128 * STAGE_ROWB)        // 18432
#define OFF_STAGE (OFF_B16 + 2 * SPLIT_TILE) // 40960
#define OFF_B1 (OFF_STAGE + 2 * STAGE_TILE)  // 77824
#define OFF_W2 (OFF_B1 + 512)
#define OFF_PART (OFF_W2 + 512)
#define SMEM_DYN (OFF_PART + 4 * 128 * 4)    // 80896
#define NCHUNK (D_ / 32)

__global__ __launch_bounds__(256, 2)
void gemm_mma_kernel(const float* __restrict__ X,
                     const float* __restrict__ b1, const float* __restrict__ W2,
                     const float* __restrict__ lengths)
{
    const int m0 = (blockIdx.x >> 2) * 128;
    {
        int b = m0 >> 12;
        int t0 = m0 & (L_ - 1);
        int alen = (int)(lengths[b] * (float)L_);
        if (t0 >= alen) return;
    }

    extern __shared__ char smem[];
    const uint32_t sb = smem_u32(smem);
    const int tid = threadIdx.x;
    const int wid = tid >> 5;
    const int lane = tid & 31;
    const int warp_m = wid >> 2;
    const int warp_n = wid & 3;
    const int quad = lane & 3;
    const int rowq = lane >> 2;

    const int nt = blockIdx.x & 3;
    const int n0 = nt * 128;

    float* s_b1 = (float*)(smem + OFF_B1);
    float* s_w2 = (float*)(smem + OFF_W2);
    float* s_part = (float*)(smem + OFF_PART);

    if (tid < 128) { s_b1[tid] = b1[n0 + tid]; s_w2[tid] = W2[n0 + tid]; }

    float acc[4][4][4];
#pragma unroll
    for (int i = 0; i < 4; ++i)
#pragma unroll
        for (int j = 0; j < 4; ++j)
#pragma unroll
            for (int k = 0; k < 4; ++k) acc[i][j][k] = 0.0f;

    const int l8 = lane & 7, sel = lane >> 3;
    const uint32_t a_row_off = (uint32_t)((l8 + (sel & 1) * 8) * ROWB + (sel >> 1) * 16);
    const uint32_t b_row_off = (uint32_t)((l8 + (sel >> 1) * 8) * ROWB + (sel & 1) * 16);

    auto issue_loads = [&](int c) {
        const int buf = c & 1;
        const int k0 = c * 32;
        const uint32_t dst_stage = sb + OFF_STAGE + buf * STAGE_TILE;
        const uint32_t dst_b = sb + OFF_B16 + buf * SPLIT_TILE;
#pragma unroll
        for (int it = 0; it < 4; ++it) {
            int i = tid + it * 256;
            int r = i >> 3;
            int q = i & 7;
            CP_ASYNC16(dst_stage + (uint32_t)(r * STAGE_ROWB + q * 16),
                       X + (size_t)(m0 + r) * D_ + k0 + q * 4);
        }
#pragma unroll
        for (int it = 0; it < 2; ++it) {
            int i = tid + it * 256;
            int r = i >> 2;
            int j = i & 3;
            CP_ASYNC16(dst_b + (uint32_t)(r * ROWB + j * 16),
                       &g_w1h[(size_t)(n0 + r) * D_ + k0 + j * 8]);
        }
        CP_COMMIT();
    };

    issue_loads(0);

    for (int c = 0; c < NCHUNK; ++c) {
        const int buf = c & 1;
        CP_WAIT(0);
        __syncthreads();

        if (c + 1 < NCHUNK) issue_loads(c + 1);

        {
            const uint32_t src = sb + OFF_STAGE + buf * STAGE_TILE;
            const uint32_t dst = sb + buf * SPLIT_TILE;
#pragma unroll
            for (int it = 0; it < 2; ++it) {
                int i = tid + it * 256;
                int r = i & 127;
                int j = i >> 7;
                uint32_t so = src + (uint32_t)(r * STAGE_ROWB + j * 32);
                float4 v0, v1;
                asm volatile("ld.shared.v4.f32 {%0,%1,%2,%3}, [%4];"
                             : "=f"(v0.x), "=f"(v0.y), "=f"(v0.z), "=f"(v0.w) : "r"(so));
                asm volatile("ld.shared.v4.f32 {%0,%1,%2,%3}, [%4];"
                             : "=f"(v1.x), "=f"(v1.y), "=f"(v1.z), "=f"(v1.w) : "r"(so + 16));
                __half2 h0 = make_half2(__float2half_rn(v0.x), __float2half_rn(v0.y));
                __half2 h1 = make_half2(__float2half_rn(v0.z), __float2half_rn(v0.w));
                __half2 h2 = make_half2(__float2half_rn(v1.x), __float2half_rn(v1.y));
                __half2 h3 = make_half2(__float2half_rn(v1.z), __float2half_rn(v1.w));
                uint32_t u0 = reinterpret_cast<uint32_t&>(h0);
                uint32_t u1 = reinterpret_cast<uint32_t&>(h1);
                uint32_t u2 = reinterpret_cast<uint32_t&>(h2);
                uint32_t u3 = reinterpret_cast<uint32_t&>(h3);
                asm volatile("st.shared.v4.b32 [%0], {%1,%2,%3,%4};"
                             :: "r"(dst + (uint32_t)(r * ROWB + j * 16)),
                                "r"(u0), "r"(u1), "r"(u2), "r"(u3));
            }
        }
        __syncthreads();

        const uint32_t sa_base = sb + buf * SPLIT_TILE + (warp_m * 64) * ROWB + a_row_off;
        const uint32_t sbb_base = sb + OFF_B16 + buf * SPLIT_TILE + (warp_n * 32) * ROWB + b_row_off;

#pragma unroll
        for (int k16 = 0; k16 < 2; ++k16) {
            uint32_t afr[16], bfr[8];
#pragma unroll
            for (int mi = 0; mi < 4; ++mi)
                ldsm4(&afr[mi * 4], sa_base + (uint32_t)(mi * 16 * ROWB + k16 * 32));
#pragma unroll
            for (int nj = 0; nj < 2; ++nj)
                ldsm4(&bfr[nj * 4], sbb_base + (uint32_t)(nj * 16 * ROWB + k16 * 32));

#pragma unroll
            for (int mi = 0; mi < 4; ++mi)
#pragma unroll
                for (int ni = 0; ni < 4; ++ni)
                    mma_f16(acc[mi][ni], &afr[mi * 4],
                            &bfr[(ni >> 1) * 4 + (ni & 1) * 2]);
        }
    }
    __syncthreads();

#pragma unroll
    for (int mi = 0; mi < 4; ++mi) {
#pragma unroll
        for (int h = 0; h < 2; ++h) {
            float p = 0.0f;
#pragma unroll
            for (int ni = 0; ni < 4; ++ni) {
#pragma unroll
                for (int cbit = 0; cbit < 2; ++cbit) {
                    int nloc = warp_n * 32 + ni * 8 + quad * 2 + cbit;
                    float v = acc[mi][ni][h * 2 + cbit] * INV_WSCALE + s_b1[nloc];
                    float g = 0.5f * v * (1.0f + erff(v * 0.7071067811865476f));
                    p = fmaf(g, s_w2[nloc], p);
                }
            }
            p += __shfl_xor_sync(0xffffffffu, p, 1);
            p += __shfl_xor_sync(0xffffffffu, p, 2);
            if (quad == 0)
                s_part[warp_n * 128 + warp_m * 64 + mi * 16 + h * 8 + rowq] = p;
        }
    }
    __syncthreads();
    if (tid < 128) {
        float r = s_part[tid] + s_part[128 + tid] + s_part[256 + tid] + s_part[384 + tid];
        g_part[nt][m0 + tid] = r;
    }
}

// ------------------------------------------------------------------
// Mega kernel: band -> recompute -> scan -> pool with resident spin barriers
// 512 threads per block. Block roles by blockIdx.x:
//   [0, 64)            band
//   [64, 128)          recompute (spins on band done)
//   [128, 136)         scan, one per batch (spins on recompute done)
//   [136, ...)         pool/tail per batch (spins on that batch's scan flag)
// ------------------------------------------------------------------
__global__ __launch_bounds__(512)
void mega_kernel(const float* __restrict__ X,      // hidden
                 const float* __restrict__ W1,
                 const float* __restrict__ b1,
                 const float* __restrict__ W2,
                 const float* __restrict__ b2,
                 const float* __restrict__ lengths,
                 int S,
                 float* __restrict__ out_masked,
                 float* __restrict__ out_short,
                 float* __restrict__ out_nb,
                 float* __restrict__ out_pooled)
{
    const int bid = blockIdx.x;
    const int tid = threadIdx.x;

    if (bid < NB_BAND) {
        // ================= BAND =================
        int gm = bid * 512 + tid;
        int b = gm >> 12;
        int t = gm & (L_ - 1);
        int alen = (int)(lengths[b] * (float)L_);
        if (t >= alen) {
            out_masked[gm] = 0.0f;
            g_hard[gm] = 0;
        } else {
            float lg = g_part[0][gm] + g_part[1][gm] + g_part[2][gm] + g_part[3][gm] + b2[0];
            float prob = 1.0f / (1.0f + expf(-lg));
            out_masked[gm] = prob;
            g_hard[gm] = (lg > 0.0f) ? 1 : 0;
            if (fabsf(lg) < BAND_TAU) {
                int idx = atomicAdd(&g_count, 1);
                g_band[idx] = gm;
            }
        }
        __threadfence();
        __syncthreads();
        if (tid == 0) atomicAdd(&g_band_done, 1);
        return;
    }

    if (bid < NB_BAND + NB_REC) {
        // ================= RECOMPUTE =================
        __shared__ float s_x[4][D_];
        __shared__ float s_red[16][4];
        if (tid == 0) spin_until(&g_band_done, NB_BAND);
        __syncthreads();
        __threadfence();

        const int rb = bid - NB_BAND;
        const int cnt = atomicAdd(&g_count, 0);

        for (int base = rb * 4; base < cnt; base += NB_REC * 4) {
            const int nrows = min(4, cnt - base);
            __syncthreads();
            for (int q = tid; q < 4 * 128; q += 512) {
                int row = q >> 7;
                int c4 = q & 127;
                float4 v = (row < nrows)
                    ? ((const float4*)(X + (size_t)g_band[base + row] * D_))[c4]
                    : make_float4(0.f, 0.f, 0.f, 0.f);
                ((float4*)s_x[row])[c4] = v;
            }
            __syncthreads();

            const int col = tid;
            float a0 = 0.f, a1 = 0.f, a2 = 0.f, a3 = 0.f;
            for (int k0 = 0; k0 < D_; k0 += 32) {
                float w[32];
#pragma unroll
                for (int j = 0; j < 32; ++j)
                    w[j] = W1[(size_t)(k0 + j) * D_ + col];
#pragma unroll
                for (int j = 0; j < 32; ++j) {
                    a0 = fmaf(s_x[0][k0 + j], w[j], a0);
                    a1 = fmaf(s_x[1][k0 + j], w[j], a1);
                    a2 = fmaf(s_x[2][k0 + j], w[j], a2);
                    a3 = fmaf(s_x[3][k0 + j], w[j], a3);
                }
            }
            float bb = b1[col], ww = W2[col];
            float av[4] = {a0, a1, a2, a3};
            float p[4];
#pragma unroll
            for (int row = 0; row < 4; ++row) {
                float v = av[row] + bb;
                float g = 0.5f * v * (1.0f + erff(v * 0.7071067811865476f));
                p[row] = g * ww;
            }
#pragma unroll
            for (int row = 0; row < 4; ++row) {
                float pr = p[row];
                for (int off = 16; off > 0; off >>= 1)
                    pr += __shfl_down_sync(0xffffffffu, pr, off);
                if ((tid & 31) == 0) s_red[tid >> 5][row] = pr;
            }
            __syncthreads();
            if (tid < nrows) {
                int row = tid;
                float lg = b2[0];
#pragma unroll
                for (int w = 0; w < 16; ++w) lg += s_red[w][row];
                int gm = g_band[base + row];
                out_masked[gm] = 1.0f / (1.0f + expf(-lg));
                g_hard[gm] = (lg > 0.0f) ? 1 : 0;
            }
        }
        __threadfence();
        __syncthreads();
        if (tid == 0) atomicAdd(&g_rec_done, 1);
        return;
    }

    if (bid < NB_BAND + NB_REC + NB_SCAN) {
        // ================= SCAN (one block per batch) =================
        __shared__ int s_wsum[16];
        __shared__ int s_end[L_];
        const int b = bid - NB_BAND - NB_REC;

        if (tid == 0) spin_until(&g_rec_done, NB_REC);
        __syncthreads();
        __threadfence();

        const int alen = (int)(lengths[b] * (float)L_);
        int last = alen - 1;
        if (last < 0) last = 0;
        if (last > L_ - 1) last = L_ - 1;

        const int base = tid * 8;
        uint2 hw = *(const uint2*)&g_hard[b * L_ + base];
        unsigned char hb[8];
        *(uint2*)hb = hw;
        int h[8];
        int loc = 0;
#pragma unroll
        for (int i = 0; i < 8; ++i) {
            int t = base + i;
            int hv = hb[i];
            if (t == last) hv = 1;
            h[i] = hv;
            loc += hv;
        }

        const int lane = tid & 31, wid = tid >> 5;
        int sc = loc;
#pragma unroll
        for (int off = 1; off < 32; off <<= 1) {
            int n = __shfl_up_sync(0xffffffffu, sc, off);
            if (lane >= off) sc += n;
        }
        if (lane == 31) s_wsum[wid] = sc;
        __syncthreads();
        if (wid == 0) {
            int w = (lane < 16) ? s_wsum[lane] : 0;
#pragma unroll
            for (int off = 1; off < 16; off <<= 1) {
                int n = __shfl_up_sync(0xffffffffu, w, off);
                if (lane >= off) w += n;
            }
            if (lane < 16) s_wsum[lane] = w;
        }
        __syncthreads();

        const int warp_off = (wid == 0) ? 0 : s_wsum[wid - 1];
        const int excl = warp_off + (sc - loc);
        const int nb = s_wsum[15];

        int run = excl;
#pragma unroll
        for (int i = 0; i < 8; ++i) {
            if (h[i]) s_end[run] = base + i;
            run += h[i];
        }
        __syncthreads();

        for (int s = tid; s < S; s += 512) {
            int st, en;
            if (s < nb) {
                en = s_end[s];
                st = (s == 0) ? 0 : (s_end[s - 1] + 1);
            } else if (s == nb) {
                st = s_end[nb - 1] + 1;   // reference quirk: invalid tail pools here
                en = L_ - 1;
            } else {
                st = 0; en = -1;
            }
            g_seg_start[b * L_ + s] = st;
            g_seg_cnt[b * L_ + s] = en - st + 1;
        }

        if (tid == 0) {
            g_nb[b] = nb;
            out_nb[b] = (float)nb;
            int sm = (S > 1) ? S : 1;
            out_short[b] = (float)nb / (float)sm;
        }
        __threadfence();
        __syncthreads();
        if (tid == 0) atomicExch(&g_scan_done[b], 1);
        return;
    }

    // ================= POOL + TAIL =================
    {
        const int pb = bid - NB_BAND - NB_REC - NB_SCAN;
        const int b = pb / (POOL_PER_B + TAIL_PER_B);
        const int bx = pb % (POOL_PER_B + TAIL_PER_B);

        if (tid == 0) spin_until(&g_scan_done[b], 1);
        __syncthreads();
        __threadfence();

        const int nb = g_nb[b];

        if (bx < POOL_PER_B) {
            const int s = bx * 16 + (tid >> 5);
            if (s >= S) return;
            if (s == nb && nb < S) return;

            const int lane = tid & 31;
            const int st  = g_seg_start[b * L_ + s];
            const int cnt = g_seg_cnt[b * L_ + s];

            const float4* base = (const float4*)(X + (size_t)b * L_ * D_);
            float4 acc[4];
#pragma unroll
            for (int p = 0; p < 4; ++p) acc[p] = make_float4(0.f, 0.f, 0.f, 0.f);
            for (int r = st; r < st + cnt; ++r) {
#pragma unroll
                for (int p = 0; p < 4; ++p) {
                    float4 v = base[(size_t)r * (D_ / 4) + p * 32 + lane];
                    acc[p].x += v.x; acc[p].y += v.y; acc[p].z += v.z; acc[p].w += v.w;
                }
            }
            float inv = 1.0f / ((float)cnt + 1e-9f);
            float4* dst = (float4*)out_pooled + ((size_t)b * S + s) * (D_ / 4);
#pragma unroll
            for (int p = 0; p < 4; ++p) {
                acc[p].x *= inv; acc[p].y *= inv; acc[p].z *= inv; acc[p].w *= inv;
                dst[p * 32 + lane] = acc[p];
            }
        } else {
            if (nb >= S) return;
            __shared__ int s_old;

            const int st  = g_seg_start[b * L_ + nb];
            const int cnt = g_seg_cnt[b * L_ + nb];
            const int quarter = tid >> 7;              // 0..3
            const int t128 = tid & 127;
            const int j = (bx - POOL_PER_B) * 4 + quarter;  // 0..15

            const float4* base = (const float4*)(X + (size_t)b * L_ * D_);
            float4 acc = make_float4(0.f, 0.f, 0.f, 0.f);
            for (int r = st + j; r < st + cnt; r += 16) {
                float4 v = base[(size_t)r * (D_ / 4) + t128];
                acc.x += v.x; acc.y += v.y; acc.z += v.z; acc.w += v.w;
            }
            ((float4*)g_tailpart[b][j])[t128] = acc;

            __threadfence();
            __syncthreads();
            if (tid == 0) s_old = atomicAdd(&g_tail_tick[b], 1);
            __syncthreads();
            if (s_old == TAIL_PER_B - 1) {
                __threadfence();
                if (tid < 128) {
                    float4 a = make_float4(0.f, 0.f, 0.f, 0.f);
#pragma unroll
                    for (int jj = 0; jj < 16; ++jj) {
                        float4 v = ((const float4*)g_tailpart[b][jj])[tid];
                        a.x += v.x; a.y += v.y; a.z += v.z; a.w += v.w;
                    }
                    float inv = 1.0f / ((float)cnt + 1e-9f);
                    a.x *= inv; a.y *= inv; a.z *= inv; a.w *= inv;
                    ((float4*)out_pooled)[((size_t)b * S + nb) * (D_ / 4) + tid] = a;
                }
            }
        }
    }
}

// ------------------------------------------------------------------
extern "C" void kernel_launch(void* const* d_in, const int* in_sizes, int n_in,
                              void* d_out, int out_size)
{
    const float* hidden  = (const float*)d_in[0];
    const float* lengths = (const float*)d_in[1];
    const float* W1      = (const float*)d_in[2];
    const float* b1      = (const float*)d_in[3];
    const float* W2      = (const float*)d_in[4];
    const float* b2      = (const float*)d_in[5];
    float* out = (float*)d_out;

    int S = (out_size - B_ * L_ - 2 * B_) / (B_ * D_);
    if (S < 1) S = 1;

    float* out_pooled = out;
    float* out_masked = out + (size_t)B_ * S * D_;
    float* out_short  = out_masked + (size_t)B_ * L_;
    float* out_nb     = out_short + B_;

    cudaFuncSetAttribute(gemm_mma_kernel, cudaFuncAttributeMaxDynamicSharedMemorySize, SMEM_DYN);

    w1half_kernel<<<D_, 512>>>(W1);                                          // 1
    gemm_mma_kernel<<<NTILES * 4, 256, SMEM_DYN>>>(hidden, b1, W2, lengths); // 2
    mega_kernel<<<MEGA_BLOCKS, 512>>>(hidden, W1, b1, W2, b2, lengths, S,
                                      out_masked, out_short, out_nb, out_pooled); // 3
}

// round 16
// speedup vs baseline: 1.1850x; 1.1850x over previous
#include <cuda_runtime.h>
#include <cuda_fp16.h>
#include <math.h>
#include <stdint.h>

#define B_  8
#define L_  4096
#define D_  512
#define M_TOTAL (B_ * L_)
#define NTILES (M_TOTAL / 128)
#define WSCALE 256.0f
#define INV_WSCALE 0.00390625f
#define BAND_TAU 1e-3f
#define POOL_BX 512

// ------------------------------------------------------------------
// device scratch
// ------------------------------------------------------------------
__device__ __half g_w1h[D_ * D_];                  // fp16(W1*256)^T [n][k]
__device__ float g_part[4][M_TOTAL];               // per-n-tile partial logits
__device__ unsigned char g_hard[M_TOTAL];          // hard boundary bits
__device__ int g_band[M_TOTAL];                    // rows needing exact recompute
__device__ int g_count;                            // band count
__device__ int g_tail_tick[B_];                    // tail completion tickets
__device__ int g_seg_start[B_ * L_];
__device__ int g_seg_cnt[B_ * L_];
__device__ int g_nb[B_];
__device__ float g_tailpart[B_][16][D_];

// ------------------------------------------------------------------
// PTX helpers (sm_80-level, safe for compute_103 non-a)
// ------------------------------------------------------------------
#define CP_ASYNC16(dst, src) \
    asm volatile("cp.async.cg.shared.global [%0], [%1], 16;" :: "r"(dst), "l"(src))
#define CP_COMMIT() asm volatile("cp.async.commit_group;")
#define CP_WAIT(n)  asm volatile("cp.async.wait_group %0;" :: "n"(n))

__device__ __forceinline__ uint32_t smem_u32(const void* p) {
    uint32_t a;
    asm("{ .reg .u64 t; cvta.to.shared.u64 t, %1; cvt.u32.u64 %0, t; }" : "=r"(a) : "l"(p));
    return a;
}
__device__ __forceinline__ void ldsm4(uint32_t* r, uint32_t a) {
    asm volatile("ldmatrix.sync.aligned.m8n8.x4.shared.b16 {%0,%1,%2,%3}, [%4];"
                 : "=r"(r[0]), "=r"(r[1]), "=r"(r[2]), "=r"(r[3]) : "r"(a));
}
__device__ __forceinline__ void mma_f16(float* c, const uint32_t* a, const uint32_t* b) {
    asm volatile(
        "mma.sync.aligned.m16n8k16.row.col.f32.f16.f16.f32 "
        "{%0,%1,%2,%3}, {%4,%5,%6,%7}, {%8,%9}, {%0,%1,%2,%3};"
        : "+f"(c[0]), "+f"(c[1]), "+f"(c[2]), "+f"(c[3])
        : "r"(a[0]), "r"(a[1]), "r"(a[2]), "r"(a[3]), "r"(b[0]), "r"(b[1]));
}

// ------------------------------------------------------------------
// Kernel B: W1 -> transposed fp16 (x256) via smem-tiled transpose;
// reset counters. Reads and writes both coalesced.
// ------------------------------------------------------------------
__global__ __launch_bounds__(256)
void w1half_kernel(const float* __restrict__ W1) {
    __shared__ __half s[32][33];
    const int tx = threadIdx.x;          // 0..31
    const int ty = threadIdx.y;          // 0..7
    const int n0 = blockIdx.x * 32;
    const int k0 = blockIdx.y * 32;

    if (blockIdx.x == 0 && blockIdx.y == 0 && ty == 0) {
        if (tx == 0) g_count = 0;
        if (tx < B_) g_tail_tick[tx] = 0;
    }

#pragma unroll
    for (int i = 0; i < 4; ++i) {
        int k = k0 + ty + i * 8;
        s[tx][ty + i * 8] = __float2half_rn(W1[(size_t)k * D_ + n0 + tx] * WSCALE);
    }
    __syncthreads();
#pragma unroll
    for (int i = 0; i < 4; ++i) {
        int n = n0 + ty + i * 8;
        g_w1h[(size_t)n * D_ + k0 + tx] = s[ty + i * 8][tx];
    }
}

// ------------------------------------------------------------------
// Kernel C: mma.sync fp16 GEMM (R9/R12/R14 anchor — unchanged)
// ------------------------------------------------------------------
#define ROWB 80
#define SPLIT_TILE (128 * ROWB)              // 10240
#define OFF_B16 (2 * SPLIT_TILE)             // 20480
#define STAGE_ROWB 144
#define STAGE_TILE (128 * STAGE_ROWB)        // 18432
#define OFF_STAGE (OFF_B16 + 2 * SPLIT_TILE) // 40960
#define OFF_B1 (OFF_STAGE + 2 * STAGE_TILE)  // 77824
#define OFF_W2 (OFF_B1 + 512)
#define OFF_PART (OFF_W2 + 512)
#define SMEM_DYN (OFF_PART + 4 * 128 * 4)    // 80896
#define NCHUNK (D_ / 32)

__global__ __launch_bounds__(256, 2)
void gemm_mma_kernel(const float* __restrict__ X,
                     const float* __restrict__ b1, const float* __restrict__ W2,
                     const float* __restrict__ lengths)
{
    const int m0 = (blockIdx.x >> 2) * 128;
    {
        int b = m0 >> 12;
        int t0 = m0 & (L_ - 1);
        int alen = (int)(lengths[b] * (float)L_);
        if (t0 >= alen) return;
    }

    extern __shared__ char smem[];
    const uint32_t sb = smem_u32(smem);
    const int tid = threadIdx.x;
    const int wid = tid >> 5;
    const int lane = tid & 31;
    const int warp_m = wid >> 2;
    const int warp_n = wid & 3;
    const int quad = lane & 3;
    const int rowq = lane >> 2;

    const int nt = blockIdx.x & 3;
    const int n0 = nt * 128;

    float* s_b1 = (float*)(smem + OFF_B1);
    float* s_w2 = (float*)(smem + OFF_W2);
    float* s_part = (float*)(smem + OFF_PART);

    if (tid < 128) { s_b1[tid] = b1[n0 + tid]; s_w2[tid] = W2[n0 + tid]; }

    float acc[4][4][4];
#pragma unroll
    for (int i = 0; i < 4; ++i)
#pragma unroll
        for (int j = 0; j < 4; ++j)
#pragma unroll
            for (int k = 0; k < 4; ++k) acc[i][j][k] = 0.0f;

    const int l8 = lane & 7, sel = lane >> 3;
    const uint32_t a_row_off = (uint32_t)((l8 + (sel & 1) * 8) * ROWB + (sel >> 1) * 16);
    const uint32_t b_row_off = (uint32_t)((l8 + (sel >> 1) * 8) * ROWB + (sel & 1) * 16);

    auto issue_loads = [&](int c) {
        const int buf = c & 1;
        const int k0 = c * 32;
        const uint32_t dst_stage = sb + OFF_STAGE + buf * STAGE_TILE;
        const uint32_t dst_b = sb + OFF_B16 + buf * SPLIT_TILE;
#pragma unroll
        for (int it = 0; it < 4; ++it) {
            int i = tid + it * 256;
            int r = i >> 3;
            int q = i & 7;
            CP_ASYNC16(dst_stage + (uint32_t)(r * STAGE_ROWB + q * 16),
                       X + (size_t)(m0 + r) * D_ + k0 + q * 4);
        }
#pragma unroll
        for (int it = 0; it < 2; ++it) {
            int i = tid + it * 256;
            int r = i >> 2;
            int j = i & 3;
            CP_ASYNC16(dst_b + (uint32_t)(r * ROWB + j * 16),
                       &g_w1h[(size_t)(n0 + r) * D_ + k0 + j * 8]);
        }
        CP_COMMIT();
    };

    issue_loads(0);

    for (int c = 0; c < NCHUNK; ++c) {
        const int buf = c & 1;
        CP_WAIT(0);
        __syncthreads();

        if (c + 1 < NCHUNK) issue_loads(c + 1);

        {
            const uint32_t src = sb + OFF_STAGE + buf * STAGE_TILE;
            const uint32_t dst = sb + buf * SPLIT_TILE;
#pragma unroll
            for (int it = 0; it < 2; ++it) {
                int i = tid + it * 256;
                int r = i & 127;
                int j = i >> 7;
                uint32_t so = src + (uint32_t)(r * STAGE_ROWB + j * 32);
                float4 v0, v1;
                asm volatile("ld.shared.v4.f32 {%0,%1,%2,%3}, [%4];"
                             : "=f"(v0.x), "=f"(v0.y), "=f"(v0.z), "=f"(v0.w) : "r"(so));
                asm volatile("ld.shared.v4.f32 {%0,%1,%2,%3}, [%4];"
                             : "=f"(v1.x), "=f"(v1.y), "=f"(v1.z), "=f"(v1.w) : "r"(so + 16));
                __half2 h0 = make_half2(__float2half_rn(v0.x), __float2half_rn(v0.y));
                __half2 h1 = make_half2(__float2half_rn(v0.z), __float2half_rn(v0.w));
                __half2 h2 = make_half2(__float2half_rn(v1.x), __float2half_rn(v1.y));
                __half2 h3 = make_half2(__float2half_rn(v1.z), __float2half_rn(v1.w));
                uint32_t u0 = reinterpret_cast<uint32_t&>(h0);
                uint32_t u1 = reinterpret_cast<uint32_t&>(h1);
                uint32_t u2 = reinterpret_cast<uint32_t&>(h2);
                uint32_t u3 = reinterpret_cast<uint32_t&>(h3);
                asm volatile("st.shared.v4.b32 [%0], {%1,%2,%3,%4};"
                             :: "r"(dst + (uint32_t)(r * ROWB + j * 16)),
                                "r"(u0), "r"(u1), "r"(u2), "r"(u3));
            }
        }
        __syncthreads();

        const uint32_t sa_base = sb + buf * SPLIT_TILE + (warp_m * 64) * ROWB + a_row_off;
        const uint32_t sbb_base = sb + OFF_B16 + buf * SPLIT_TILE + (warp_n * 32) * ROWB + b_row_off;

#pragma unroll
        for (int k16 = 0; k16 < 2; ++k16) {
            uint32_t afr[16], bfr[8];
#pragma unroll
            for (int mi = 0; mi < 4; ++mi)
                ldsm4(&afr[mi * 4], sa_base + (uint32_t)(mi * 16 * ROWB + k16 * 32));
#pragma unroll
            for (int nj = 0; nj < 2; ++nj)
                ldsm4(&bfr[nj * 4], sbb_base + (uint32_t)(nj * 16 * ROWB + k16 * 32));

#pragma unroll
            for (int mi = 0; mi < 4; ++mi)
#pragma unroll
                for (int ni = 0; ni < 4; ++ni)
                    mma_f16(acc[mi][ni], &afr[mi * 4],
                            &bfr[(ni >> 1) * 4 + (ni & 1) * 2]);
        }
    }
    __syncthreads();

#pragma unroll
    for (int mi = 0; mi < 4; ++mi) {
#pragma unroll
        for (int h = 0; h < 2; ++h) {
            float p = 0.0f;
#pragma unroll
            for (int ni = 0; ni < 4; ++ni) {
#pragma unroll
                for (int cbit = 0; cbit < 2; ++cbit) {
                    int nloc = warp_n * 32 + ni * 8 + quad * 2 + cbit;
                    float v = acc[mi][ni][h * 2 + cbit] * INV_WSCALE + s_b1[nloc];
                    float g = 0.5f * v * (1.0f + erff(v * 0.7071067811865476f));
                    p = fmaf(g, s_w2[nloc], p);
                }
            }
            p += __shfl_xor_sync(0xffffffffu, p, 1);
            p += __shfl_xor_sync(0xffffffffu, p, 2);
            if (quad == 0)
                s_part[warp_n * 128 + warp_m * 64 + mi * 16 + h * 8 + rowq] = p;
        }
    }
    __syncthreads();
    if (tid < 128) {
        float r = s_part[tid] + s_part[128 + tid] + s_part[256 + tid] + s_part[384 + tid];
        g_part[nt][m0 + tid] = r;
    }
}

// ------------------------------------------------------------------
// Kernel D: logits -> probs/hard bits; collect near-threshold band rows
// ------------------------------------------------------------------
__global__ __launch_bounds__(512)
void band_kernel(const float* __restrict__ lengths, const float* __restrict__ b2,
                 float* __restrict__ out_masked)
{
    int gm = blockIdx.x * 512 + threadIdx.x;
    int b = gm >> 12;
    int t = gm & (L_ - 1);
    int alen = (int)(lengths[b] * (float)L_);
    if (t >= alen) {
        out_masked[gm] = 0.0f;
        g_hard[gm] = 0;
        return;
    }
    float lg = g_part[0][gm] + g_part[1][gm] + g_part[2][gm] + g_part[3][gm] + b2[0];
    float prob = 1.0f / (1.0f + expf(-lg));
    out_masked[gm] = prob;
    g_hard[gm] = (lg > 0.0f) ? 1 : 0;
    if (fabsf(lg) < BAND_TAU) {
        int idx = atomicAdd(&g_count, 1);
        g_band[idx] = gm;
    }
}

// ------------------------------------------------------------------
// Kernel E: exact fp32 recompute, 4 rows/block, 512 threads, MLP-32
// ------------------------------------------------------------------
__global__ __launch_bounds__(512)
void recompute_kernel(const float* __restrict__ X, const float* __restrict__ W1,
                      const float* __restrict__ b1, const float* __restrict__ W2,
                      const float* __restrict__ b2, float* __restrict__ out_masked)
{
    __shared__ float s_x[4][D_];
    __shared__ float s_red[16][4];
    const int tid = threadIdx.x;
    const int cnt = g_count;

    for (int base = blockIdx.x * 4; base < cnt; base += gridDim.x * 4) {
        const int nrows = min(4, cnt - base);
        __syncthreads();
        for (int q = tid; q < 4 * 128; q += 512) {
            int row = q >> 7;
            int c4 = q & 127;
            float4 v = (row < nrows)
                ? ((const float4*)(X + (size_t)g_band[base + row] * D_))[c4]
                : make_float4(0.f, 0.f, 0.f, 0.f);
            ((float4*)s_x[row])[c4] = v;
        }
        __syncthreads();

        const int col = tid;
        float a0 = 0.f, a1 = 0.f, a2 = 0.f, a3 = 0.f;
        for (int k0 = 0; k0 < D_; k0 += 32) {
            float w[32];
#pragma unroll
            for (int j = 0; j < 32; ++j)
                w[j] = W1[(size_t)(k0 + j) * D_ + col];
#pragma unroll
            for (int j = 0; j < 32; ++j) {
                a0 = fmaf(s_x[0][k0 + j], w[j], a0);
                a1 = fmaf(s_x[1][k0 + j], w[j], a1);
                a2 = fmaf(s_x[2][k0 + j], w[j], a2);
                a3 = fmaf(s_x[3][k0 + j], w[j], a3);
            }
        }
        float bb = b1[col], ww = W2[col];
        float av[4] = {a0, a1, a2, a3};
        float p[4];
#pragma unroll
        for (int row = 0; row < 4; ++row) {
            float v = av[row] + bb;
            float g = 0.5f * v * (1.0f + erff(v * 0.7071067811865476f));
            p[row] = g * ww;
        }
#pragma unroll
        for (int row = 0; row < 4; ++row) {
            float pr = p[row];
            for (int off = 16; off > 0; off >>= 1)
                pr += __shfl_down_sync(0xffffffffu, pr, off);
            if ((tid & 31) == 0) s_red[tid >> 5][row] = pr;
        }
        __syncthreads();
        if (tid < nrows) {
            int row = tid;
            float lg = b2[0];
#pragma unroll
            for (int w = 0; w < 16; ++w) lg += s_red[w][row];
            int gm = g_band[base + row];
            out_masked[gm] = 1.0f / (1.0f + expf(-lg));
            g_hard[gm] = (lg > 0.0f) ? 1 : 0;
        }
    }
}

// ------------------------------------------------------------------
// Kernel F: scan hard bits -> segment table
// ------------------------------------------------------------------
__global__ __launch_bounds__(512)
void scan_kernel(const float* __restrict__ lengths, int S,
                 float* __restrict__ out_short, float* __restrict__ out_nb)
{
    const int b = blockIdx.x;
    const int tid = threadIdx.x;
    __shared__ int s_wsum[16];
    __shared__ int s_end[L_];

    const int alen = (int)(lengths[b] * (float)L_);
    int last = alen - 1;
    if (last < 0) last = 0;
    if (last > L_ - 1) last = L_ - 1;

    const int base = tid * 8;
    uint2 hw = *(const uint2*)&g_hard[b * L_ + base];
    unsigned char hb[8];
    *(uint2*)hb = hw;
    int h[8];
    int loc = 0;
#pragma unroll
    for (int i = 0; i < 8; ++i) {
        int t = base + i;
        int hv = hb[i];
        if (t == last) hv = 1;
        h[i] = hv;
        loc += hv;
    }

    const int lane = tid & 31, wid = tid >> 5;
    int sc = loc;
#pragma unroll
    for (int off = 1; off < 32; off <<= 1) {
        int n = __shfl_up_sync(0xffffffffu, sc, off);
        if (lane >= off) sc += n;
    }
    if (lane == 31) s_wsum[wid] = sc;
    __syncthreads();
    if (wid == 0) {
        int w = (lane < 16) ? s_wsum[lane] : 0;
#pragma unroll
        for (int off = 1; off < 16; off <<= 1) {
            int n = __shfl_up_sync(0xffffffffu, w, off);
            if (lane >= off) w += n;
        }
        if (lane < 16) s_wsum[lane] = w;
    }
    __syncthreads();

    const int warp_off = (wid == 0) ? 0 : s_wsum[wid - 1];
    const int excl = warp_off + (sc - loc);
    const int nb = s_wsum[15];

    int run = excl;
#pragma unroll
    for (int i = 0; i < 8; ++i) {
        if (h[i]) s_end[run] = base + i;
        run += h[i];
    }
    __syncthreads();

    for (int s = tid; s < S; s += 512) {
        int st, en;
        if (s < nb) {
            en = s_end[s];
            st = (s == 0) ? 0 : (s_end[s - 1] + 1);
        } else if (s == nb) {
            st = s_end[nb - 1] + 1;   // reference quirk: invalid tail pools here
            en = L_ - 1;
        } else {
            st = 0; en = -1;
        }
        g_seg_start[b * L_ + s] = st;
        g_seg_cnt[b * L_ + s] = en - st + 1;
    }

    if (tid == 0) {
        g_nb[b] = nb;
        out_nb[b] = (float)nb;
        int sm = (S > 1) ? S : 1;
        out_short[b] = (float)nb / (float)sm;
    }
}

// ------------------------------------------------------------------
// Kernel G: fused segment mean-pool + tail reduction (R12/R14 structure)
// ------------------------------------------------------------------
__global__ __launch_bounds__(256)
void pool_kernel(const float* __restrict__ hidden, int S, float* __restrict__ out_pooled)
{
    const int b = blockIdx.y;
    const int bx = blockIdx.x;
    const int nb = g_nb[b];

    if (bx < POOL_BX) {
        const int s = bx * 8 + (threadIdx.x >> 5);
        if (s >= S) return;
        if (s == nb && nb < S) return;

        const int lane = threadIdx.x & 31;
        const int st  = g_seg_start[b * L_ + s];
        const int cnt = g_seg_cnt[b * L_ + s];

        const float4* base = (const float4*)(hidden + (size_t)b * L_ * D_);
        float4 acc[4];
#pragma unroll
        for (int p = 0; p < 4; ++p) acc[p] = make_float4(0.f, 0.f, 0.f, 0.f);
        for (int r = st; r < st + cnt; ++r) {
#pragma unroll
            for (int p = 0; p < 4; ++p) {
                float4 v = base[(size_t)r * (D_ / 4) + p * 32 + lane];
                acc[p].x += v.x; acc[p].y += v.y; acc[p].z += v.z; acc[p].w += v.w;
            }
        }
        float inv = 1.0f / ((float)cnt + 1e-9f);
        float4* dst = (float4*)out_pooled + ((size_t)b * S + s) * (D_ / 4);
#pragma unroll
        for (int p = 0; p < 4; ++p) {
            acc[p].x *= inv; acc[p].y *= inv; acc[p].z *= inv; acc[p].w *= inv;
            dst[p * 32 + lane] = acc[p];
        }
    } else {
        if (nb >= S) return;
        const int tid = threadIdx.x;
        __shared__ int s_old;

        const int st  = g_seg_start[b * L_ + nb];
        const int cnt = g_seg_cnt[b * L_ + nb];
        const int half = tid >> 7;
        const int t128 = tid & 127;
        const int j = (bx - POOL_BX) * 2 + half;

        const float4* base = (const float4*)(hidden + (size_t)b * L_ * D_);
        float4 acc = make_float4(0.f, 0.f, 0.f, 0.f);
        for (int r = st + j; r < st + cnt; r += 16) {
            float4 v = base[(size_t)r * (D_ / 4) + t128];
            acc.x += v.x; acc.y += v.y; acc.z += v.z; acc.w += v.w;
        }
        ((float4*)g_tailpart[b][j])[t128] = acc;

        __threadfence();
        __syncthreads();
        if (tid == 0) s_old = atomicAdd(&g_tail_tick[b], 1);
        __syncthreads();
        if (s_old == 7) {
            __threadfence();
            if (tid < 128) {
                float4 a = make_float4(0.f, 0.f, 0.f, 0.f);
#pragma unroll
                for (int jj = 0; jj < 16; ++jj) {
                    float4 v = ((const float4*)g_tailpart[b][jj])[tid];
                    a.x += v.x; a.y += v.y; a.z += v.z; a.w += v.w;
                }
                float inv = 1.0f / ((float)cnt + 1e-9f);
                a.x *= inv; a.y *= inv; a.z *= inv; a.w *= inv;
                ((float4*)out_pooled)[((size_t)b * S + nb) * (D_ / 4) + tid] = a;
            }
        }
    }
}

// ------------------------------------------------------------------
extern "C" void kernel_launch(void* const* d_in, const int* in_sizes, int n_in,
                              void* d_out, int out_size)
{
    const float* hidden  = (const float*)d_in[0];
    const float* lengths = (const float*)d_in[1];
    const float* W1      = (const float*)d_in[2];
    const float* b1      = (const float*)d_in[3];
    const float* W2      = (const float*)d_in[4];
    const float* b2      = (const float*)d_in[5];
    float* out = (float*)d_out;

    int S = (out_size - B_ * L_ - 2 * B_) / (B_ * D_);
    if (S < 1) S = 1;

    float* out_pooled = out;
    float* out_masked = out + (size_t)B_ * S * D_;
    float* out_short  = out_masked + (size_t)B_ * L_;
    float* out_nb     = out_short + B_;

    cudaFuncSetAttribute(gemm_mma_kernel, cudaFuncAttributeMaxDynamicSharedMemorySize, SMEM_DYN);

    w1half_kernel<<<dim3(16, 16), dim3(32, 8)>>>(W1);                        // 1
    gemm_mma_kernel<<<NTILES * 4, 256, SMEM_DYN>>>(hidden, b1, W2, lengths); // 2
    band_kernel<<<M_TOTAL / 512, 512>>>(lengths, b2, out_masked);            // 3
    recompute_kernel<<<128, 512>>>(hidden, W1, b1, W2, b2, out_masked);      // 4 (profiled)
    scan_kernel<<<B_, 512>>>(lengths, S, out_short, out_nb);                 // 5
    pool_kernel<<<dim3(POOL_BX + 8, B_), 256>>>(hidden, S, out_pooled);      // 6
}